// round 9
// baseline (speedup 1.0000x reference)
#include <cuda_runtime.h>

// GumbelVQ forward on GB300 (sm_103a).  Best passing: R6 @ 258.6us.
//
//  - st = y_hard numerically  =>  z_q = embedding[argmax_k(logits + gumbel)]
//  - JAX (threefry_partitionable=True) counter-mode noise: for linear element
//    index i over (N,K):  (o0,o1) = threefry2x32(key=(0,42), (0,i)),
//    bits = o0 ^ o1.  u = bitcast((bits>>9)|0x3f800000)-1 clamped to 1e-20.
//    gumbel = -log(-log u).  argmax first-occurrence.
//  - Filter: g <= -ilogb(1-u)*ln2; only candidates that can beat the warp's
//    running max pay exact logs (~10 per row of 8192).
//  - R8: 4 elements per ballot envelope (amortize control, 4 indep threefry
//    chains for ILP); counts via distributed global atomics; final kernel
//    self-rezeros g_counts so no zero-kernel launch is needed.

#define NUM_CODES 8192
#define NROWS     8192

__device__ float g_row_commit[NROWS];
__device__ int   g_counts[NUM_CODES];     // zero at start; re-zeroed each run

__device__ __forceinline__ unsigned rotl(unsigned x, int r) {
    return __funnelshift_l(x, x, r);
}

// threefry2x32, key (0,42), input (0, i), 20 rounds, output o0^o1.
__device__ __forceinline__ unsigned tf_bits(unsigned i) {
    const unsigned C = 0x1BD11BF0u;          // 0 ^ 42 ^ 0x1BD11BDA
    unsigned x0, x1;
    x1 = i + 42u;
    x0 = x1;                                 // round-1 add with x0 = 0
    x1 = rotl(x1, 13) ^ x0;
    x0 += x1; x1 = rotl(x1, 15) ^ x0;
    x0 += x1; x1 = rotl(x1, 26) ^ x0;
    x0 += x1; x1 = rotl(x1,  6) ^ x0;
    x1 += C + 1u;
    x0 += 42u + x1;
    x1 = rotl(x1, 17) ^ x0;
    x0 += x1; x1 = rotl(x1, 29) ^ x0;
    x0 += x1; x1 = rotl(x1, 16) ^ x0;
    x0 += x1; x1 = rotl(x1, 24) ^ x0;
    x1 += 2u;
    x0 += C + x1;
    x1 = rotl(x1, 13) ^ x0;
    x0 += x1; x1 = rotl(x1, 15) ^ x0;
    x0 += x1; x1 = rotl(x1, 26) ^ x0;
    x0 += x1; x1 = rotl(x1,  6) ^ x0;
    x1 += 45u;
    x0 += x1;
    x1 = rotl(x1, 17) ^ x0;
    x0 += x1; x1 = rotl(x1, 29) ^ x0;
    x0 += x1; x1 = rotl(x1, 16) ^ x0;
    x0 += x1; x1 = rotl(x1, 24) ^ x0;
    x1 += C + 4u;
    x0 += 42u + x1;
    x1 = rotl(x1, 13) ^ x0;
    x0 += x1; x1 = rotl(x1, 15) ^ x0;
    x0 += x1; x1 = rotl(x1, 26) ^ x0;
    x0 += x1; x1 = rotl(x1,  6) ^ x0;
    return (x0 + C) ^ (x1 + 5u);
}

// exact gumbel from f = 1+u in [1,2): winners have u~1, use log1p there so the
// inner log keeps full relative accuracy even under fast-math.
__device__ __forceinline__ float gumbel_exact(float f) {
    float u = fmaxf(f - 1.0f, 1e-20f);
    float e = (f > 1.5f) ? (-log1pf(f - 2.0f)) : (-logf(u));
    return -logf(e);
}

// ub(gumbel) precursor: fe = -ilogb(1-u) as float, via exponent-bias trick.
__device__ __forceinline__ float ub_fe(float f) {
    const float v = 2.0f - f;                               // = 1-u (Sterbenz)
    const int   e = 127 - (int)(__float_as_uint(v) >> 23);  // 0..23
    return __uint_as_float((unsigned)e | 0x4B000000u) - 8388608.0f;
}

__global__ void __launch_bounds__(256, 2) vq_argmax_kernel(
    const float* __restrict__ z_e,
    const float* __restrict__ emb,
    const float* __restrict__ proj,
    float* __restrict__ out,
    int has_idx)
{
    const int lane = threadIdx.x & 31;
    const int warp = threadIdx.x >> 5;
    const int n    = blockIdx.x * 8 + warp;       // one row per warp
    const int b    = n >> 10, hw = n & 1023;      // z_e is (8, 8, 32, 32)

    float z[8];
#pragma unroll
    for (int d = 0; d < 8; d++)
        z[d] = z_e[b * 8192 + d * 1024 + hw];

    const float NEG = -3.0e38f;
    float madj = NEG;                 // (warp running max) - 4e-6 slack
    float best = NEG;
    int   bi   = 0;
    unsigned cnt = (unsigned)n * (unsigned)NUM_CODES + (unsigned)lane;
    const float4* __restrict__ proj4 = (const float4*)proj;

    for (int j = 0; j < NUM_CODES / 32; j += 4) {
        const int kb = j * 32 + lane;

        unsigned bits[4];
#pragma unroll
        for (int c = 0; c < 4; c++)
            bits[c] = tf_bits(cnt + 32u * c);    // 4 independent chains (ILP)
        cnt += 128u;

        float f[4], fe[4], l[4];
#pragma unroll
        for (int c = 0; c < 4; c++) {
            f[c]  = __uint_as_float((bits[c] >> 9) | 0x3f800000u);
            fe[c] = ub_fe(f[c]);
        }
#pragma unroll
        for (int c = 0; c < 4; c++) {
            const int k = kb + 32 * c;
            const float4 wa = __ldg(proj4 + k * 2);
            const float4 wb = __ldg(proj4 + k * 2 + 1);
            float s = z[0] * wa.x;
            s = fmaf(z[1], wa.y, s); s = fmaf(z[2], wa.z, s);
            s = fmaf(z[3], wa.w, s); s = fmaf(z[4], wb.x, s);
            s = fmaf(z[5], wb.y, s); s = fmaf(z[6], wb.z, s);
            s = fmaf(z[7], wb.w, s);
            l[c] = s;
        }

        // 0.69314724 > ln2 rounds the bound up; madj carries -4e-6 slack so
        // FFMA rounding can never drop a true winner.
        bool p[4]; bool any = false;
#pragma unroll
        for (int c = 0; c < 4; c++) {
            p[c] = fmaf(fe[c], 0.69314724f, l[c]) > madj;
            any |= p[c];
        }
        if (__ballot_sync(0xffffffffu, any)) {
            float sm = NEG;
#pragma unroll
            for (int c = 0; c < 4; c++) {        // ascending k: first-occ kept
                if (p[c]) {
                    float s = l[c] + gumbel_exact(f[c]);
                    if (s > best) { best = s; bi = kb + 32 * c; }
                    sm = fmaxf(sm, s);
                }
            }
#pragma unroll
            for (int o = 16; o > 0; o >>= 1)
                sm = fmaxf(sm, __shfl_xor_sync(0xffffffffu, sm, o));
            sm -= 4e-6f;
            if (sm > madj) madj = sm;
        }
    }

    // cross-lane argmax; ties -> smaller k (first occurrence, jnp.argmax)
#pragma unroll
    for (int o = 16; o > 0; o >>= 1) {
        float ob = __shfl_xor_sync(0xffffffffu, best, o);
        int   oi = __shfl_xor_sync(0xffffffffu, bi,   o);
        if (ob > best || (ob == best && oi < bi)) { best = ob; bi = oi; }
    }

    // outputs: z_q gather, per-row commit sum, counts, idx
    float sq = 0.0f;
    if (lane < 8) {
        float ev = emb[bi * 8 + lane];
        out[b * 8192 + lane * 1024 + hw] = ev;
        float dd = z[lane] - ev;
        sq = dd * dd;
    }
#pragma unroll
    for (int o = 16; o > 0; o >>= 1)
        sq += __shfl_xor_sync(0xffffffffu, sq, o);
    if (lane == 0) {
        g_row_commit[n] = sq;
        atomicAdd(&g_counts[bi], 1);
        if (has_idx) out[65536 + n] = (float)bi;
    }
}

__global__ void __launch_bounds__(512) vq_final_kernel(float* __restrict__ out,
                                                       int has_scalars) {
    __shared__ float sp[512];
    __shared__ float sc[512];
    __shared__ int   su[512];
    const int t = threadIdx.x;
    float plog = 0.0f, csum = 0.0f;
    int used = 0;
    for (int k = t; k < NUM_CODES; k += 512) {
        int c = g_counts[k];
        g_counts[k] = 0;                     // leave zeroed for next replay
        if (c > 0) {
            float avg = (float)c * (1.0f / 8192.0f);
            plog += avg * logf(avg + 1e-10f);
            used++;
        }
        csum += g_row_commit[k];             // NROWS == NUM_CODES
    }
    sp[t] = plog; sc[t] = csum; su[t] = used;
    __syncthreads();
    for (int s = 256; s > 0; s >>= 1) {
        if (t < s) { sp[t] += sp[t + s]; sc[t] += sc[t + s]; su[t] += su[t + s]; }
        __syncthreads();
    }
    if (t == 0 && has_scalars) {
        out[73728] = 0.25f * (sc[0] * (1.0f / 65536.0f));  // commit_loss
        out[73729] = expf(-sp[0]);                         // perplexity
        out[73730] = (float)su[0] * (1.0f / 8192.0f);      // usage
    }
}

extern "C" void kernel_launch(void* const* d_in, const int* in_sizes, int n_in,
                              void* d_out, int out_size) {
    const float* z_e  = (const float*)d_in[0];
    const float* emb  = (const float*)d_in[1];
    const float* proj = (const float*)d_in[2];
    float* out = (float*)d_out;
    int has_idx     = (out_size >= 65536 + 8192) ? 1 : 0;
    int has_scalars = (out_size >= 65536 + 8192 + 3) ? 1 : 0;

    vq_argmax_kernel<<<NROWS / 8, 256>>>(z_e, emb, proj, out, has_idx);
    vq_final_kernel<<<1, 512>>>(out, has_scalars);
}